// round 3
// baseline (speedup 1.0000x reference)
#include <cuda_runtime.h>

#define NN 50000
#define NE 800000

// ---------------- scratch (static device globals; no allocation) ----------------
__device__ __align__(16) float g_buf1[NN * 256];  // h1 (N,256) then h2 (N,128)
__device__ __align__(16) float g_buf2[NN * 256];  // h (N,256) then h_emb (N,128)
__device__ float g_dinv[NN];
__device__ int   g_deg[NN];
__device__ int   g_cur[NN];
__device__ int   g_off[NN + 1];
__device__ int   g_srcs[NE];
__device__ float g_gacc[128];

// ---------------- small setup kernels ----------------
__global__ void init_kernel() {
    int i = blockIdx.x * blockDim.x + threadIdx.x;
    if (i < NN) { g_deg[i] = 0; g_cur[i] = 0; }
    if (i < 128) g_gacc[i] = 0.f;
}

__global__ void deg_kernel(const int* __restrict__ dst) {
    int e = blockIdx.x * blockDim.x + threadIdx.x;
    if (e < NE) atomicAdd(&g_deg[dst[e]], 1);
}

__global__ void dinv_kernel() {
    int i = blockIdx.x * blockDim.x + threadIdx.x;
    if (i < NN) g_dinv[i] = rsqrtf((float)(g_deg[i] + 1));
}

__global__ void scan_kernel() {
    __shared__ int sh[1024];
    int tid = threadIdx.x;
    const int chunk = (NN + 1023) / 1024;
    int start = tid * chunk;
    int end = min(start + chunk, NN);
    int s = 0;
    for (int i = start; i < end; i++) s += g_deg[i];
    sh[tid] = s;
    __syncthreads();
    for (int o = 1; o < 1024; o <<= 1) {
        int v = (tid >= o) ? sh[tid - o] : 0;
        __syncthreads();
        sh[tid] += v;
        __syncthreads();
    }
    int excl = sh[tid] - s;
    for (int i = start; i < end; i++) { g_off[i] = excl; excl += g_deg[i]; }
    if (tid == 1023) g_off[NN] = sh[1023];
}

__global__ void fill_kernel(const int* __restrict__ src, const int* __restrict__ dst) {
    int e = blockIdx.x * blockDim.x + threadIdx.x;
    if (e < NE) {
        int d = dst[e];
        int p = atomicAdd(&g_cur[d], 1);
        g_srcs[g_off[d] + p] = src[e];
    }
}

// ---------------- fp32 SGEMM: C[M,N] = A[M,K] @ B[K,N], all row-major ----------------
// BM=128, BN=64, BK=16, 256 threads, 8x4 per thread.
__global__ __launch_bounds__(256) void sgemm_kernel(
    const float* __restrict__ A, const float* __restrict__ B, float* __restrict__ C,
    int M, int N, int K)
{
    __shared__ float As[16][128];
    __shared__ float Bs[16][64];
    const int tid = threadIdx.x;
    const int tx = tid & 15;      // 0..15 -> N
    const int ty = tid >> 4;      // 0..15 -> M
    const int m0 = blockIdx.y * 128;
    const int n0 = blockIdx.x * 64;

    float acc[8][4];
#pragma unroll
    for (int i = 0; i < 8; i++)
#pragma unroll
        for (int j = 0; j < 4; j++) acc[i][j] = 0.f;

    for (int k0 = 0; k0 < K; k0 += 16) {
        // load A tile (128x16) transposed into As[k][m]
#pragma unroll
        for (int i = 0; i < 2; i++) {
            int f = tid + i * 256;          // 0..511
            int ar = f >> 2;                // 0..127
            int kc = (f & 3) * 4;           // 0,4,8,12
            int gr = m0 + ar;
            float4 v = make_float4(0.f, 0.f, 0.f, 0.f);
            if (gr < M) v = *(const float4*)(A + (size_t)gr * K + k0 + kc);
            As[kc + 0][ar] = v.x;
            As[kc + 1][ar] = v.y;
            As[kc + 2][ar] = v.z;
            As[kc + 3][ar] = v.w;
        }
        // load B tile (16x64)
        {
            int br = tid >> 4;              // 0..15
            int bc = (tid & 15) * 4;        // 0..60
            float4 v = *(const float4*)(B + (size_t)(k0 + br) * N + n0 + bc);
            *(float4*)&Bs[br][bc] = v;
        }
        __syncthreads();
#pragma unroll
        for (int kk = 0; kk < 16; kk++) {
            float a[8], b[4];
#pragma unroll
            for (int j = 0; j < 8; j++) a[j] = As[kk][ty * 8 + j];
#pragma unroll
            for (int j = 0; j < 4; j++) b[j] = Bs[kk][tx * 4 + j];
#pragma unroll
            for (int i = 0; i < 8; i++)
#pragma unroll
                for (int j = 0; j < 4; j++) acc[i][j] = fmaf(a[i], b[j], acc[i][j]);
        }
        __syncthreads();
    }
#pragma unroll
    for (int i = 0; i < 8; i++) {
        int gr = m0 + ty * 8 + i;
        if (gr < M) {
            float4 v = make_float4(acc[i][0], acc[i][1], acc[i][2], acc[i][3]);
            *(float4*)(C + (size_t)gr * N + n0 + tx * 4) = v;
        }
    }
}

// ---------------- layer-1 aggregation (256-dim), warp per node, grid-stride ----------------
__global__ __launch_bounds__(256) void agg1_kernel(
    const float* __restrict__ h1, const float* __restrict__ bias, float* __restrict__ out)
{
    const int tid = threadIdx.x;
    const int lane = tid & 31;
    int warp = (blockIdx.x * blockDim.x + tid) >> 5;
    const int nw = (gridDim.x * blockDim.x) >> 5;
    const float4* __restrict__ H = (const float4*)h1;
    float4 bs0 = ((const float4*)bias)[lane];
    float4 bs1 = ((const float4*)bias)[lane + 32];
    for (int d = warp; d < NN; d += nw) {
        float dd = g_dinv[d];
        int e0 = g_off[d], e1 = g_off[d + 1];
        float4 a0 = make_float4(0.f, 0.f, 0.f, 0.f);
        float4 a1 = make_float4(0.f, 0.f, 0.f, 0.f);
        for (int e = e0; e < e1; e++) {
            int s = g_srcs[e];
            float nm = g_dinv[s] * dd;
            size_t base = (size_t)s * 64;
            float4 v0 = H[base + lane];
            float4 v1 = H[base + lane + 32];
            a0.x = fmaf(v0.x, nm, a0.x); a0.y = fmaf(v0.y, nm, a0.y);
            a0.z = fmaf(v0.z, nm, a0.z); a0.w = fmaf(v0.w, nm, a0.w);
            a1.x = fmaf(v1.x, nm, a1.x); a1.y = fmaf(v1.y, nm, a1.y);
            a1.z = fmaf(v1.z, nm, a1.z); a1.w = fmaf(v1.w, nm, a1.w);
        }
        float sn = dd * dd;
        size_t sb = (size_t)d * 64;
        float4 v0 = H[sb + lane];
        float4 v1 = H[sb + lane + 32];
        a0.x = fmaf(v0.x, sn, a0.x); a0.y = fmaf(v0.y, sn, a0.y);
        a0.z = fmaf(v0.z, sn, a0.z); a0.w = fmaf(v0.w, sn, a0.w);
        a1.x = fmaf(v1.x, sn, a1.x); a1.y = fmaf(v1.y, sn, a1.y);
        a1.z = fmaf(v1.z, sn, a1.z); a1.w = fmaf(v1.w, sn, a1.w);
        float4 r0, r1;
        r0.x = fmaxf(a0.x + bs0.x, 0.f); r0.y = fmaxf(a0.y + bs0.y, 0.f);
        r0.z = fmaxf(a0.z + bs0.z, 0.f); r0.w = fmaxf(a0.w + bs0.w, 0.f);
        r1.x = fmaxf(a1.x + bs1.x, 0.f); r1.y = fmaxf(a1.y + bs1.y, 0.f);
        r1.z = fmaxf(a1.z + bs1.z, 0.f); r1.w = fmaxf(a1.w + bs1.w, 0.f);
        ((float4*)out)[sb + lane] = r0;
        ((float4*)out)[sb + lane + 32] = r1;
    }
}

// ---------------- layer-2 aggregation (128-dim) fused with node_logits + mean partial ----------------
__global__ __launch_bounds__(256) void agg2_fused_kernel(
    const float* __restrict__ h2, const float* __restrict__ bias,
    const float* __restrict__ npW, const float* __restrict__ npb,
    float* __restrict__ hemb, float* __restrict__ node_logits)
{
    __shared__ float gsum[128];
    const int tid = threadIdx.x;
    if (tid < 128) gsum[tid] = 0.f;
    __syncthreads();

    const int lane = tid & 31;
    int warp = (blockIdx.x * blockDim.x + tid) >> 5;
    const int nw = (gridDim.x * blockDim.x) >> 5;
    const int k = lane * 4;

    float w0[4], w1[4], w2[4];
#pragma unroll
    for (int j = 0; j < 4; j++) {
        w0[j] = npW[(k + j) * 3 + 0];
        w1[j] = npW[(k + j) * 3 + 1];
        w2[j] = npW[(k + j) * 3 + 2];
    }
    float nb0 = npb[0], nb1 = npb[1], nb2 = npb[2];
    float4 bs = ((const float4*)bias)[lane];
    float gl0 = 0.f, gl1 = 0.f, gl2 = 0.f, gl3 = 0.f;
    const float4* __restrict__ H = (const float4*)h2;

    for (int d = warp; d < NN; d += nw) {
        float dd = g_dinv[d];
        int e0 = g_off[d], e1 = g_off[d + 1];
        float4 acc = make_float4(0.f, 0.f, 0.f, 0.f);
        for (int e = e0; e < e1; e++) {
            int s = g_srcs[e];
            float nm = g_dinv[s] * dd;
            float4 v = H[(size_t)s * 32 + lane];
            acc.x = fmaf(v.x, nm, acc.x); acc.y = fmaf(v.y, nm, acc.y);
            acc.z = fmaf(v.z, nm, acc.z); acc.w = fmaf(v.w, nm, acc.w);
        }
        float sn = dd * dd;
        float4 v = H[(size_t)d * 32 + lane];
        acc.x = fmaf(v.x, sn, acc.x); acc.y = fmaf(v.y, sn, acc.y);
        acc.z = fmaf(v.z, sn, acc.z); acc.w = fmaf(v.w, sn, acc.w);
        acc.x = fmaxf(acc.x + bs.x, 0.f); acc.y = fmaxf(acc.y + bs.y, 0.f);
        acc.z = fmaxf(acc.z + bs.z, 0.f); acc.w = fmaxf(acc.w + bs.w, 0.f);
        ((float4*)hemb)[(size_t)d * 32 + lane] = acc;

        gl0 += acc.x; gl1 += acc.y; gl2 += acc.z; gl3 += acc.w;

        float l0 = acc.x * w0[0] + acc.y * w0[1] + acc.z * w0[2] + acc.w * w0[3];
        float l1 = acc.x * w1[0] + acc.y * w1[1] + acc.z * w1[2] + acc.w * w1[3];
        float l2 = acc.x * w2[0] + acc.y * w2[1] + acc.z * w2[2] + acc.w * w2[3];
#pragma unroll
        for (int o = 16; o > 0; o >>= 1) {
            l0 += __shfl_down_sync(0xffffffffu, l0, o);
            l1 += __shfl_down_sync(0xffffffffu, l1, o);
            l2 += __shfl_down_sync(0xffffffffu, l2, o);
        }
        if (lane == 0) {
            node_logits[(size_t)d * 3 + 0] = l0 + nb0;
            node_logits[(size_t)d * 3 + 1] = l1 + nb1;
            node_logits[(size_t)d * 3 + 2] = l2 + nb2;
        }
    }
    atomicAdd(&gsum[k + 0], gl0);
    atomicAdd(&gsum[k + 1], gl1);
    atomicAdd(&gsum[k + 2], gl2);
    atomicAdd(&gsum[k + 3], gl3);
    __syncthreads();
    if (tid < 128) atomicAdd(&g_gacc[tid], gsum[tid]);
}

// ---------------- edge head: warp per edge, grid-stride ----------------
__global__ __launch_bounds__(256) void edge_kernel(
    const float* __restrict__ h, const int* __restrict__ src, const int* __restrict__ dst,
    const float* __restrict__ epW, const float* __restrict__ epb, float* __restrict__ out)
{
    const int tid = threadIdx.x;
    const int lane = tid & 31;
    int warp = (blockIdx.x * blockDim.x + tid) >> 5;
    const int nw = (gridDim.x * blockDim.x) >> 5;
    const int k = lane * 4;
    float ws0[4], ws1[4], wd0[4], wd1[4];
#pragma unroll
    for (int j = 0; j < 4; j++) {
        ws0[j] = epW[(k + j) * 2 + 0];
        ws1[j] = epW[(k + j) * 2 + 1];
        wd0[j] = epW[(128 + k + j) * 2 + 0];
        wd1[j] = epW[(128 + k + j) * 2 + 1];
    }
    float b0 = epb[0], b1 = epb[1];
    const float4* __restrict__ H = (const float4*)h;
    for (int e = warp; e < NE; e += nw) {
        int s = src[e], d = dst[e];
        float4 vs = H[(size_t)s * 32 + lane];
        float4 vd = H[(size_t)d * 32 + lane];
        float a0 = vs.x * ws0[0] + vs.y * ws0[1] + vs.z * ws0[2] + vs.w * ws0[3]
                 + vd.x * wd0[0] + vd.y * wd0[1] + vd.z * wd0[2] + vd.w * wd0[3];
        float a1 = vs.x * ws1[0] + vs.y * ws1[1] + vs.z * ws1[2] + vs.w * ws1[3]
                 + vd.x * wd1[0] + vd.y * wd1[1] + vd.z * wd1[2] + vd.w * wd1[3];
#pragma unroll
        for (int o = 16; o > 0; o >>= 1) {
            a0 += __shfl_down_sync(0xffffffffu, a0, o);
            a1 += __shfl_down_sync(0xffffffffu, a1, o);
        }
        if (lane == 0) {
            out[(size_t)e * 2 + 0] = a0 + b0;
            out[(size_t)e * 2 + 1] = a1 + b1;
        }
    }
}

// ---------------- tiny global heads (value, global_logits) ----------------
__global__ __launch_bounds__(256) void head_kernel(
    const float* __restrict__ fc1W, const float* __restrict__ fc1b,
    const float* __restrict__ fc2W, const float* __restrict__ fc2b,
    const float* __restrict__ gpW, const float* __restrict__ gpb,
    float* __restrict__ out_glob, float* __restrict__ out_value)
{
    __shared__ float g[128];
    __shared__ float vsh[256];
    __shared__ float red[8];
    const int t = threadIdx.x;
    const int lane = t & 31, wid = t >> 5;
    if (t < 128) g[t] = g_gacc[t] * (1.0f / (float)NN);
    __syncthreads();

    float acc = 0.f;
    for (int kk = 0; kk < 128; kk++) acc = fmaf(g[kk], fc1W[kk * 256 + t], acc);
    vsh[t] = fmaxf(acc + fc1b[t], 0.f);
    __syncthreads();

    // value = vsh . fc2W + fc2b
    float p = vsh[t] * fc2W[t];
#pragma unroll
    for (int o = 16; o > 0; o >>= 1) p += __shfl_down_sync(0xffffffffu, p, o);
    if (lane == 0) red[wid] = p;
    __syncthreads();
    if (t == 0) {
        float tot = 0.f;
        for (int i = 0; i < 8; i++) tot += red[i];
        out_value[0] = tot + fc2b[0];
    }
    __syncthreads();

    // global_logits = g . gpW + gpb
    float q = (t < 128) ? g[t] * gpW[t] : 0.f;
#pragma unroll
    for (int o = 16; o > 0; o >>= 1) q += __shfl_down_sync(0xffffffffu, q, o);
    if (lane == 0) red[wid] = q;
    __syncthreads();
    if (t == 0) {
        float tot = 0.f;
        for (int i = 0; i < 8; i++) tot += red[i];
        out_glob[0] = tot + gpb[0];
    }
}

// ---------------- launch ----------------
extern "C" void kernel_launch(void* const* d_in, const int* in_sizes, int n_in,
                              void* d_out, int out_size)
{
    const float* x    = (const float*)d_in[0];
    const int*   ei   = (const int*)d_in[1];
    const float* W1   = (const float*)d_in[2];
    const float* b1   = (const float*)d_in[3];
    const float* W2   = (const float*)d_in[4];
    const float* b2   = (const float*)d_in[5];
    const float* fc1W = (const float*)d_in[6];
    const float* fc1b = (const float*)d_in[7];
    const float* fc2W = (const float*)d_in[8];
    const float* fc2b = (const float*)d_in[9];
    const float* npW  = (const float*)d_in[10];
    const float* npb  = (const float*)d_in[11];
    const float* epW  = (const float*)d_in[12];
    const float* epb  = (const float*)d_in[13];
    const float* gpW  = (const float*)d_in[14];
    const float* gpb  = (const float*)d_in[15];

    float* out = (float*)d_out;
    float* out_node  = out;
    float* out_edge  = out + (size_t)NN * 3;
    float* out_glob  = out + (size_t)NN * 3 + (size_t)NE * 2;
    float* out_value = out_glob + 1;

    const int* src = ei;
    const int* dst = ei + NE;

    float* buf1; float* buf2;
    cudaGetSymbolAddress((void**)&buf1, g_buf1);
    cudaGetSymbolAddress((void**)&buf2, g_buf2);

    init_kernel<<<(NN + 255) / 256, 256>>>();
    deg_kernel<<<(NE + 255) / 256, 256>>>(dst);
    dinv_kernel<<<(NN + 255) / 256, 256>>>();
    scan_kernel<<<1, 1024>>>();
    fill_kernel<<<(NE + 255) / 256, 256>>>(src, dst);

    // h1 = x @ W1   [N,256]
    sgemm_kernel<<<dim3(256 / 64, (NN + 127) / 128), 256>>>(x, W1, buf1, NN, 256, 128);
    // h = relu(agg(h1) + b1)  [N,256]
    agg1_kernel<<<1024, 256>>>(buf1, b1, buf2);
    // h2 = h @ W2   [N,128]
    sgemm_kernel<<<dim3(128 / 64, (NN + 127) / 128), 256>>>(buf2, W2, buf1, NN, 128, 256);
    // h_emb = relu(agg(h2) + b2); also node_logits + mean partials
    agg2_fused_kernel<<<1024, 256>>>(buf1, b2, npW, npb, buf2, out_node);
    // edge logits
    edge_kernel<<<2048, 256>>>(buf2, src, dst, epW, epb, out_edge);
    // value + global logits
    head_kernel<<<1, 256>>>(fc1W, fc1b, fc2W, fc2b, gpW, gpb, out_glob, out_value);
}

// round 5
// speedup vs baseline: 1.0687x; 1.0687x over previous
#include <cuda_runtime.h>

#define NN 50000
#define NE 800000
#define NB 49   // ceil(NN/1024)

// ---------------- scratch (static device globals; no allocation) ----------------
__device__ __align__(16) float g_buf1[NN * 256];  // zx (N,128) -> h2 (N,128)
__device__ __align__(16) float g_buf2[NN * 256];  // h (N,256) -> h_emb (N,128)
__device__ float g_dinv[NN];
__device__ int   g_deg[NN];
__device__ int   g_cur[NN];
__device__ int   g_off[NN + 1];
__device__ int   g_bsum[NB];
__device__ int   g_srcs[NE];
__device__ float g_gacc[128];

// ---------------- setup ----------------
__global__ void deg_kernel(const int* __restrict__ dst) {
    int e = blockIdx.x * blockDim.x + threadIdx.x;
    if (e < NE) atomicAdd(&g_deg[dst[e]], 1);
}

// Block-level scan: per-block exclusive prefix into g_off, block total into g_bsum.
// Also computes dinv. 49 blocks x 1024.
__global__ __launch_bounds__(1024) void scan1_kernel() {
    __shared__ int wsum[32];
    int i = blockIdx.x * 1024 + threadIdx.x;
    int d = (i < NN) ? g_deg[i] : 0;
    if (i < NN) g_dinv[i] = rsqrtf((float)(d + 1));
    int lane = threadIdx.x & 31, w = threadIdx.x >> 5;
    int v = d;
#pragma unroll
    for (int o = 1; o < 32; o <<= 1) {
        int t = __shfl_up_sync(0xffffffffu, v, o);
        if (lane >= o) v += t;
    }
    if (lane == 31) wsum[w] = v;
    __syncthreads();
    if (w == 0) {
        int s = wsum[lane];
#pragma unroll
        for (int o = 1; o < 32; o <<= 1) {
            int t = __shfl_up_sync(0xffffffffu, s, o);
            if (lane >= o) s += t;
        }
        wsum[lane] = s;
    }
    __syncthreads();
    int excl = v - d + (w > 0 ? wsum[w - 1] : 0);
    if (i < NN) g_off[i] = excl;
    if (threadIdx.x == 1023) g_bsum[blockIdx.x] = wsum[31];
}

// Add per-block base (recomputed redundantly by 64 threads per block). 49 blocks x 1024.
__global__ __launch_bounds__(1024) void scan2_kernel() {
    __shared__ int red[2];
    int t = threadIdx.x;
    if (t < 64) {
        int v = (t < blockIdx.x) ? g_bsum[t] : 0;
#pragma unroll
        for (int o = 16; o > 0; o >>= 1) v += __shfl_down_sync(0xffffffffu, v, o);
        if ((t & 31) == 0) red[t >> 5] = v;
    }
    __syncthreads();
    int base = red[0] + red[1];
    int i = blockIdx.x * 1024 + t;
    if (i < NN) g_off[i] += base;
    if (blockIdx.x == 0 && t == 0) g_off[NN] = NE;
}

__global__ void fill_kernel(const int* __restrict__ src, const int* __restrict__ dst) {
    int e = blockIdx.x * blockDim.x + threadIdx.x;
    if (e < NE) {
        int d = dst[e];
        int p = atomicAdd(&g_cur[d], 1);
        g_srcs[g_off[d] + p] = src[e];
    }
}

// ---------------- layer-1 pre-aggregation on x (128-dim), warp per node ----------------
__global__ __launch_bounds__(256) void aggx_kernel(const float* __restrict__ x,
                                                   float* __restrict__ z)
{
    int warp = (blockIdx.x * 256 + threadIdx.x) >> 5;
    int lane = threadIdx.x & 31;
    if (warp >= NN) return;
    const float4* __restrict__ X = (const float4*)x;
    int d = warp;
    float dd = g_dinv[d];
    int e0 = g_off[d], e1 = g_off[d + 1];
    float4 acc = make_float4(0.f, 0.f, 0.f, 0.f);
    for (int e = e0; e < e1; e++) {
        int s = g_srcs[e];
        float nm = g_dinv[s] * dd;
        float4 v = X[(size_t)s * 32 + lane];
        acc.x = fmaf(v.x, nm, acc.x); acc.y = fmaf(v.y, nm, acc.y);
        acc.z = fmaf(v.z, nm, acc.z); acc.w = fmaf(v.w, nm, acc.w);
    }
    float sn = dd * dd;
    float4 v = X[(size_t)d * 32 + lane];
    acc.x = fmaf(v.x, sn, acc.x); acc.y = fmaf(v.y, sn, acc.y);
    acc.z = fmaf(v.z, sn, acc.z); acc.w = fmaf(v.w, sn, acc.w);
    ((float4*)z)[(size_t)d * 32 + lane] = acc;
}

// ---------------- fp32 SGEMM 128x128x16, 8x8/thread, optional bias+relu epilogue ----------------
// C[M,N] = op(A[M,K] @ B[K,N] (+ bias)), row-major. N multiple of 128, K multiple of 16.
__global__ __launch_bounds__(256) void sgemm128_kernel(
    const float* __restrict__ A, const float* __restrict__ B, float* __restrict__ C,
    const float* __restrict__ bias, int relu, int M, int N, int K)
{
    __shared__ float As[16][128];
    __shared__ float Bs[16][128];
    const int tid = threadIdx.x;
    const int tx = tid & 15;      // N: 8 cols each
    const int ty = tid >> 4;      // M: 8 rows each
    const int m0 = blockIdx.y * 128;
    const int n0 = blockIdx.x * 128;

    float acc[8][8];
#pragma unroll
    for (int i = 0; i < 8; i++)
#pragma unroll
        for (int j = 0; j < 8; j++) acc[i][j] = 0.f;

    for (int k0 = 0; k0 < K; k0 += 16) {
        // A tile 128x16 -> As[k][m] (transposed)
#pragma unroll
        for (int i = 0; i < 2; i++) {
            int f = tid + i * 256;          // 0..511
            int ar = f >> 2;                // 0..127
            int kc = (f & 3) * 4;
            int gr = m0 + ar;
            float4 v = make_float4(0.f, 0.f, 0.f, 0.f);
            if (gr < M) v = *(const float4*)(A + (size_t)gr * K + k0 + kc);
            As[kc + 0][ar] = v.x;
            As[kc + 1][ar] = v.y;
            As[kc + 2][ar] = v.z;
            As[kc + 3][ar] = v.w;
        }
        // B tile 16x128 -> Bs
#pragma unroll
        for (int i = 0; i < 2; i++) {
            int f = tid + i * 256;          // 0..511
            int br = f >> 5;                // 0..15
            int bc = (f & 31) * 4;          // 0..124
            *(float4*)&Bs[br][bc] = *(const float4*)(B + (size_t)(k0 + br) * N + n0 + bc);
        }
        __syncthreads();
#pragma unroll
        for (int kk = 0; kk < 16; kk++) {
            float4 a0 = *(const float4*)&As[kk][ty * 8];
            float4 a1 = *(const float4*)&As[kk][ty * 8 + 4];
            float4 b0 = *(const float4*)&Bs[kk][tx * 8];
            float4 b1 = *(const float4*)&Bs[kk][tx * 8 + 4];
            float a[8] = {a0.x, a0.y, a0.z, a0.w, a1.x, a1.y, a1.z, a1.w};
            float b[8] = {b0.x, b0.y, b0.z, b0.w, b1.x, b1.y, b1.z, b1.w};
#pragma unroll
            for (int i = 0; i < 8; i++)
#pragma unroll
                for (int j = 0; j < 8; j++) acc[i][j] = fmaf(a[i], b[j], acc[i][j]);
        }
        __syncthreads();
    }

    float4 bb0 = make_float4(0.f, 0.f, 0.f, 0.f);
    float4 bb1 = make_float4(0.f, 0.f, 0.f, 0.f);
    if (bias) {
        bb0 = *(const float4*)(bias + n0 + tx * 8);
        bb1 = *(const float4*)(bias + n0 + tx * 8 + 4);
    }
#pragma unroll
    for (int i = 0; i < 8; i++) {
        int gr = m0 + ty * 8 + i;
        if (gr < M) {
            float4 r0, r1;
            r0.x = acc[i][0] + bb0.x; r0.y = acc[i][1] + bb0.y;
            r0.z = acc[i][2] + bb0.z; r0.w = acc[i][3] + bb0.w;
            r1.x = acc[i][4] + bb1.x; r1.y = acc[i][5] + bb1.y;
            r1.z = acc[i][6] + bb1.z; r1.w = acc[i][7] + bb1.w;
            if (relu) {
                r0.x = fmaxf(r0.x, 0.f); r0.y = fmaxf(r0.y, 0.f);
                r0.z = fmaxf(r0.z, 0.f); r0.w = fmaxf(r0.w, 0.f);
                r1.x = fmaxf(r1.x, 0.f); r1.y = fmaxf(r1.y, 0.f);
                r1.z = fmaxf(r1.z, 0.f); r1.w = fmaxf(r1.w, 0.f);
            }
            *(float4*)(C + (size_t)gr * N + n0 + tx * 8) = r0;
            *(float4*)(C + (size_t)gr * N + n0 + tx * 8 + 4) = r1;
        }
    }
}

// ---------------- layer-2 aggregation (128-dim) fused with node_logits + mean partial ----------------
__global__ __launch_bounds__(256) void agg2_fused_kernel(
    const float* __restrict__ h2, const float* __restrict__ bias,
    const float* __restrict__ npW, const float* __restrict__ npb,
    float* __restrict__ hemb, float* __restrict__ node_logits)
{
    __shared__ float gsum[128];
    const int tid = threadIdx.x;
    if (tid < 128) gsum[tid] = 0.f;
    __syncthreads();

    const int lane = tid & 31;
    int warp = (blockIdx.x * blockDim.x + tid) >> 5;
    const int nw = (gridDim.x * blockDim.x) >> 5;
    const int k = lane * 4;

    float w0[4], w1[4], w2[4];
#pragma unroll
    for (int j = 0; j < 4; j++) {
        w0[j] = npW[(k + j) * 3 + 0];
        w1[j] = npW[(k + j) * 3 + 1];
        w2[j] = npW[(k + j) * 3 + 2];
    }
    float nb0 = npb[0], nb1 = npb[1], nb2 = npb[2];
    float4 bs = ((const float4*)bias)[lane];
    float gl0 = 0.f, gl1 = 0.f, gl2 = 0.f, gl3 = 0.f;
    const float4* __restrict__ H = (const float4*)h2;

    for (int d = warp; d < NN; d += nw) {
        float dd = g_dinv[d];
        int e0 = g_off[d], e1 = g_off[d + 1];
        float4 acc = make_float4(0.f, 0.f, 0.f, 0.f);
        for (int e = e0; e < e1; e++) {
            int s = g_srcs[e];
            float nm = g_dinv[s] * dd;
            float4 v = H[(size_t)s * 32 + lane];
            acc.x = fmaf(v.x, nm, acc.x); acc.y = fmaf(v.y, nm, acc.y);
            acc.z = fmaf(v.z, nm, acc.z); acc.w = fmaf(v.w, nm, acc.w);
        }
        float sn = dd * dd;
        float4 v = H[(size_t)d * 32 + lane];
        acc.x = fmaf(v.x, sn, acc.x); acc.y = fmaf(v.y, sn, acc.y);
        acc.z = fmaf(v.z, sn, acc.z); acc.w = fmaf(v.w, sn, acc.w);
        acc.x = fmaxf(acc.x + bs.x, 0.f); acc.y = fmaxf(acc.y + bs.y, 0.f);
        acc.z = fmaxf(acc.z + bs.z, 0.f); acc.w = fmaxf(acc.w + bs.w, 0.f);
        ((float4*)hemb)[(size_t)d * 32 + lane] = acc;

        gl0 += acc.x; gl1 += acc.y; gl2 += acc.z; gl3 += acc.w;

        float l0 = acc.x * w0[0] + acc.y * w0[1] + acc.z * w0[2] + acc.w * w0[3];
        float l1 = acc.x * w1[0] + acc.y * w1[1] + acc.z * w1[2] + acc.w * w1[3];
        float l2 = acc.x * w2[0] + acc.y * w2[1] + acc.z * w2[2] + acc.w * w2[3];
#pragma unroll
        for (int o = 16; o > 0; o >>= 1) {
            l0 += __shfl_down_sync(0xffffffffu, l0, o);
            l1 += __shfl_down_sync(0xffffffffu, l1, o);
            l2 += __shfl_down_sync(0xffffffffu, l2, o);
        }
        if (lane == 0) {
            node_logits[(size_t)d * 3 + 0] = l0 + nb0;
            node_logits[(size_t)d * 3 + 1] = l1 + nb1;
            node_logits[(size_t)d * 3 + 2] = l2 + nb2;
        }
    }
    atomicAdd(&gsum[k + 0], gl0);
    atomicAdd(&gsum[k + 1], gl1);
    atomicAdd(&gsum[k + 2], gl2);
    atomicAdd(&gsum[k + 3], gl3);
    __syncthreads();
    if (tid < 128) atomicAdd(&g_gacc[tid], gsum[tid]);
}

// ---------------- edge head: warp per edge, grid-stride ----------------
__global__ __launch_bounds__(256) void edge_kernel(
    const float* __restrict__ h, const int* __restrict__ src, const int* __restrict__ dst,
    const float* __restrict__ epW, const float* __restrict__ epb, float* __restrict__ out)
{
    const int tid = threadIdx.x;
    const int lane = tid & 31;
    int warp = (blockIdx.x * blockDim.x + tid) >> 5;
    const int nw = (gridDim.x * blockDim.x) >> 5;
    const int k = lane * 4;
    float ws0[4], ws1[4], wd0[4], wd1[4];
#pragma unroll
    for (int j = 0; j < 4; j++) {
        ws0[j] = epW[(k + j) * 2 + 0];
        ws1[j] = epW[(k + j) * 2 + 1];
        wd0[j] = epW[(128 + k + j) * 2 + 0];
        wd1[j] = epW[(128 + k + j) * 2 + 1];
    }
    float b0 = epb[0], b1 = epb[1];
    const float4* __restrict__ H = (const float4*)h;
    for (int e = warp; e < NE; e += nw) {
        int s = src[e], d = dst[e];
        float4 vs = H[(size_t)s * 32 + lane];
        float4 vd = H[(size_t)d * 32 + lane];
        float a0 = vs.x * ws0[0] + vs.y * ws0[1] + vs.z * ws0[2] + vs.w * ws0[3]
                 + vd.x * wd0[0] + vd.y * wd0[1] + vd.z * wd0[2] + vd.w * wd0[3];
        float a1 = vs.x * ws1[0] + vs.y * ws1[1] + vs.z * ws1[2] + vs.w * ws1[3]
                 + vd.x * wd1[0] + vd.y * wd1[1] + vd.z * wd1[2] + vd.w * wd1[3];
#pragma unroll
        for (int o = 16; o > 0; o >>= 1) {
            a0 += __shfl_down_sync(0xffffffffu, a0, o);
            a1 += __shfl_down_sync(0xffffffffu, a1, o);
        }
        if (lane == 0) {
            out[(size_t)e * 2 + 0] = a0 + b0;
            out[(size_t)e * 2 + 1] = a1 + b1;
        }
    }
}

// ---------------- tiny global heads (value, global_logits) ----------------
__global__ __launch_bounds__(256) void head_kernel(
    const float* __restrict__ fc1W, const float* __restrict__ fc1b,
    const float* __restrict__ fc2W, const float* __restrict__ fc2b,
    const float* __restrict__ gpW, const float* __restrict__ gpb,
    float* __restrict__ out_glob, float* __restrict__ out_value)
{
    __shared__ float g[128];
    __shared__ float vsh[256];
    __shared__ float red[8];
    const int t = threadIdx.x;
    const int lane = t & 31, wid = t >> 5;
    if (t < 128) g[t] = g_gacc[t] * (1.0f / (float)NN);
    __syncthreads();

    float acc = 0.f;
    for (int kk = 0; kk < 128; kk++) acc = fmaf(g[kk], fc1W[kk * 256 + t], acc);
    vsh[t] = fmaxf(acc + fc1b[t], 0.f);
    __syncthreads();

    float p = vsh[t] * fc2W[t];
#pragma unroll
    for (int o = 16; o > 0; o >>= 1) p += __shfl_down_sync(0xffffffffu, p, o);
    if (lane == 0) red[wid] = p;
    __syncthreads();
    if (t == 0) {
        float tot = 0.f;
        for (int i = 0; i < 8; i++) tot += red[i];
        out_value[0] = tot + fc2b[0];
    }
    __syncthreads();

    float q = (t < 128) ? g[t] * gpW[t] : 0.f;
#pragma unroll
    for (int o = 16; o > 0; o >>= 1) q += __shfl_down_sync(0xffffffffu, q, o);
    if (lane == 0) red[wid] = q;
    __syncthreads();
    if (t == 0) {
        float tot = 0.f;
        for (int i = 0; i < 8; i++) tot += red[i];
        out_glob[0] = tot + gpb[0];
    }
}

// ---------------- launch ----------------
extern "C" void kernel_launch(void* const* d_in, const int* in_sizes, int n_in,
                              void* d_out, int out_size)
{
    const float* x    = (const float*)d_in[0];
    const int*   ei   = (const int*)d_in[1];
    const float* W1   = (const float*)d_in[2];
    const float* b1   = (const float*)d_in[3];
    const float* W2   = (const float*)d_in[4];
    const float* b2   = (const float*)d_in[5];
    const float* fc1W = (const float*)d_in[6];
    const float* fc1b = (const float*)d_in[7];
    const float* fc2W = (const float*)d_in[8];
    const float* fc2b = (const float*)d_in[9];
    const float* npW  = (const float*)d_in[10];
    const float* npb  = (const float*)d_in[11];
    const float* epW  = (const float*)d_in[12];
    const float* epb  = (const float*)d_in[13];
    const float* gpW  = (const float*)d_in[14];
    const float* gpb  = (const float*)d_in[15];

    float* out = (float*)d_out;
    float* out_node  = out;
    float* out_edge  = out + (size_t)NN * 3;
    float* out_glob  = out + (size_t)NN * 3 + (size_t)NE * 2;
    float* out_value = out_glob + 1;

    const int* src = ei;
    const int* dst = ei + NE;

    float* buf1; float* buf2;
    void* p;
    cudaGetSymbolAddress(&p, g_buf1); buf1 = (float*)p;
    cudaGetSymbolAddress(&p, g_buf2); buf2 = (float*)p;
    void* pdeg;  cudaGetSymbolAddress(&pdeg, g_deg);
    void* pcur;  cudaGetSymbolAddress(&pcur, g_cur);
    void* pgacc; cudaGetSymbolAddress(&pgacc, g_gacc);

    cudaMemsetAsync(pdeg, 0, NN * sizeof(int));
    cudaMemsetAsync(pcur, 0, NN * sizeof(int));
    cudaMemsetAsync(pgacc, 0, 128 * sizeof(float));

    deg_kernel<<<(NE + 255) / 256, 256>>>(dst);
    scan1_kernel<<<NB, 1024>>>();
    scan2_kernel<<<NB, 1024>>>();
    fill_kernel<<<(NE + 255) / 256, 256>>>(src, dst);

    // zx = A_hat @ x   [N,128]  (aggregate BEFORE the linear layer — GCN is linear)
    aggx_kernel<<<(NN * 32 + 255) / 256, 256>>>(x, buf1);
    // h = relu(zx @ W1 + b1)  [N,256]
    sgemm128_kernel<<<dim3(2, (NN + 127) / 128), 256>>>(buf1, W1, buf2, b1, 1, NN, 256, 128);
    // h2 = h @ W2  [N,128]
    sgemm128_kernel<<<dim3(1, (NN + 127) / 128), 256>>>(buf2, W2, buf1, nullptr, 0, NN, 128, 256);
    // h_emb = relu(agg(h2) + b2); node_logits; mean partials
    agg2_fused_kernel<<<1024, 256>>>(buf1, b2, npW, npb, buf2, out_node);
    // edge logits
    edge_kernel<<<2048, 256>>>(buf2, src, dst, epW, epb, out_edge);
    // value + global logits
    head_kernel<<<1, 256>>>(fc1W, fc1b, fc2W, fc2b, gpW, gpb, out_glob, out_value);
}

// round 6
// speedup vs baseline: 1.6819x; 1.5738x over previous
#include <cuda_runtime.h>

#define NN 50000
#define NE 800000
#define NB 49   // ceil(NN/1024)

// ---------------- scratch (static device globals; no allocation) ----------------
__device__ __align__(16) float g_buf1[NN * 256];  // zx (N,128) -> h2 (N,128)
__device__ __align__(16) float g_buf2[NN * 256];  // h (N,256) -> h_emb (N,128)
__device__ __align__(16) float4 g_proj[NN];       // per-node edge projections (ps0,ps1,pd0,pd1)
__device__ float g_dinv[NN];
__device__ int   g_deg[NN];
__device__ int   g_cur[NN];
__device__ int   g_off[NN + 1];
__device__ int   g_bsum[NB];
__device__ int   g_srcs[NE];
__device__ float g_gacc[128];

// ---------------- setup ----------------
__global__ void deg_kernel(const int* __restrict__ dst) {
    int e = blockIdx.x * blockDim.x + threadIdx.x;
    if (e < NE) atomicAdd(&g_deg[dst[e]], 1);
}

// Block-level scan: per-block exclusive prefix into g_off, block total into g_bsum.
__global__ __launch_bounds__(1024) void scan1_kernel() {
    __shared__ int wsum[32];
    int i = blockIdx.x * 1024 + threadIdx.x;
    int d = (i < NN) ? g_deg[i] : 0;
    if (i < NN) g_dinv[i] = rsqrtf((float)(d + 1));
    int lane = threadIdx.x & 31, w = threadIdx.x >> 5;
    int v = d;
#pragma unroll
    for (int o = 1; o < 32; o <<= 1) {
        int t = __shfl_up_sync(0xffffffffu, v, o);
        if (lane >= o) v += t;
    }
    if (lane == 31) wsum[w] = v;
    __syncthreads();
    if (w == 0) {
        int s = wsum[lane];
#pragma unroll
        for (int o = 1; o < 32; o <<= 1) {
            int t = __shfl_up_sync(0xffffffffu, s, o);
            if (lane >= o) s += t;
        }
        wsum[lane] = s;
    }
    __syncthreads();
    int excl = v - d + (w > 0 ? wsum[w - 1] : 0);
    if (i < NN) g_off[i] = excl;
    if (threadIdx.x == 1023) g_bsum[blockIdx.x] = wsum[31];
}

__global__ __launch_bounds__(1024) void scan2_kernel() {
    __shared__ int red[2];
    int t = threadIdx.x;
    if (t < 64) {
        int v = (t < blockIdx.x) ? g_bsum[t] : 0;
#pragma unroll
        for (int o = 16; o > 0; o >>= 1) v += __shfl_down_sync(0xffffffffu, v, o);
        if ((t & 31) == 0) red[t >> 5] = v;
    }
    __syncthreads();
    int base = red[0] + red[1];
    int i = blockIdx.x * 1024 + t;
    if (i < NN) g_off[i] += base;
    if (blockIdx.x == 0 && t == 0) g_off[NN] = NE;
}

__global__ void fill_kernel(const int* __restrict__ src, const int* __restrict__ dst) {
    int e = blockIdx.x * blockDim.x + threadIdx.x;
    if (e < NE) {
        int d = dst[e];
        int p = atomicAdd(&g_cur[d], 1);
        g_srcs[g_off[d] + p] = src[e];
    }
}

// ---------------- layer-1 pre-aggregation on x (128-dim), warp per node ----------------
__global__ __launch_bounds__(256) void aggx_kernel(const float* __restrict__ x,
                                                   float* __restrict__ z)
{
    int warp = (blockIdx.x * 256 + threadIdx.x) >> 5;
    int lane = threadIdx.x & 31;
    if (warp >= NN) return;
    const float4* __restrict__ X = (const float4*)x;
    int d = warp;
    float dd = g_dinv[d];
    int e0 = g_off[d], e1 = g_off[d + 1];
    float4 acc = make_float4(0.f, 0.f, 0.f, 0.f);
    for (int e = e0; e < e1; e++) {
        int s = g_srcs[e];
        float nm = g_dinv[s] * dd;
        float4 v = X[(size_t)s * 32 + lane];
        acc.x = fmaf(v.x, nm, acc.x); acc.y = fmaf(v.y, nm, acc.y);
        acc.z = fmaf(v.z, nm, acc.z); acc.w = fmaf(v.w, nm, acc.w);
    }
    float sn = dd * dd;
    float4 v = X[(size_t)d * 32 + lane];
    acc.x = fmaf(v.x, sn, acc.x); acc.y = fmaf(v.y, sn, acc.y);
    acc.z = fmaf(v.z, sn, acc.z); acc.w = fmaf(v.w, sn, acc.w);
    ((float4*)z)[(size_t)d * 32 + lane] = acc;
}

// ---------------- fp32 SGEMM 128x128x16, 8x8/thread, double-buffered smem ----------------
// C[M,N] = op(A[M,K] @ B[K,N] (+ bias)), row-major. N multiple of 128, K multiple of 16.
__global__ __launch_bounds__(256) void sgemm128_kernel(
    const float* __restrict__ A, const float* __restrict__ B, float* __restrict__ C,
    const float* __restrict__ bias, int relu, int M, int N, int K)
{
    __shared__ float As[2][16][128];
    __shared__ float Bs[2][16][128];
    const int tid = threadIdx.x;
    const int tx = tid & 15;      // N: 8 cols each
    const int ty = tid >> 4;      // M: 8 rows each
    const int m0 = blockIdx.y * 128;
    const int n0 = blockIdx.x * 128;

    // loader coordinates (2 float4 each for A and B per tile)
    const int ar0 = tid >> 2;            // 0..63
    const int ar1 = (tid + 256) >> 2;    // 64..127
    const int akc = (tid & 3) * 4;
    const int br0 = tid >> 5;            // 0..7
    const int br1 = (tid + 256) >> 5;    // 8..15
    const int bbc = (tid & 31) * 4;

    const bool am0 = (m0 + ar0) < M;
    const bool am1 = (m0 + ar1) < M;
    const float* Ap0 = A + (size_t)(m0 + ar0) * K + akc;
    const float* Ap1 = A + (size_t)(m0 + ar1) * K + akc;
    const float* Bp0 = B + (size_t)br0 * N + n0 + bbc;
    const float* Bp1 = B + (size_t)br1 * N + n0 + bbc;

    float acc[8][8];
#pragma unroll
    for (int i = 0; i < 8; i++)
#pragma unroll
        for (int j = 0; j < 8; j++) acc[i][j] = 0.f;

    const int nt = K >> 4;
    float4 pa0, pa1, pb0, pb1;

    // prologue: load tile 0
    pa0 = am0 ? *(const float4*)(Ap0) : make_float4(0.f, 0.f, 0.f, 0.f);
    pa1 = am1 ? *(const float4*)(Ap1) : make_float4(0.f, 0.f, 0.f, 0.f);
    pb0 = *(const float4*)(Bp0);
    pb1 = *(const float4*)(Bp1);
    As[0][akc + 0][ar0] = pa0.x; As[0][akc + 1][ar0] = pa0.y;
    As[0][akc + 2][ar0] = pa0.z; As[0][akc + 3][ar0] = pa0.w;
    As[0][akc + 0][ar1] = pa1.x; As[0][akc + 1][ar1] = pa1.y;
    As[0][akc + 2][ar1] = pa1.z; As[0][akc + 3][ar1] = pa1.w;
    *(float4*)&Bs[0][br0][bbc] = pb0;
    *(float4*)&Bs[0][br1][bbc] = pb1;
    __syncthreads();

    for (int it = 0; it < nt; it++) {
        const int cur = it & 1;
        const int nxt = cur ^ 1;
        if (it + 1 < nt) {
            int k0 = (it + 1) << 4;
            pa0 = am0 ? *(const float4*)(Ap0 + k0) : make_float4(0.f, 0.f, 0.f, 0.f);
            pa1 = am1 ? *(const float4*)(Ap1 + k0) : make_float4(0.f, 0.f, 0.f, 0.f);
            pb0 = *(const float4*)(Bp0 + (size_t)k0 * N);
            pb1 = *(const float4*)(Bp1 + (size_t)k0 * N);
        }
#pragma unroll
        for (int kk = 0; kk < 16; kk++) {
            float4 a0 = *(const float4*)&As[cur][kk][ty * 8];
            float4 a1 = *(const float4*)&As[cur][kk][ty * 8 + 4];
            float4 b0 = *(const float4*)&Bs[cur][kk][tx * 8];
            float4 b1 = *(const float4*)&Bs[cur][kk][tx * 8 + 4];
            float a[8] = {a0.x, a0.y, a0.z, a0.w, a1.x, a1.y, a1.z, a1.w};
            float b[8] = {b0.x, b0.y, b0.z, b0.w, b1.x, b1.y, b1.z, b1.w};
#pragma unroll
            for (int i = 0; i < 8; i++)
#pragma unroll
                for (int j = 0; j < 8; j++) acc[i][j] = fmaf(a[i], b[j], acc[i][j]);
        }
        if (it + 1 < nt) {
            As[nxt][akc + 0][ar0] = pa0.x; As[nxt][akc + 1][ar0] = pa0.y;
            As[nxt][akc + 2][ar0] = pa0.z; As[nxt][akc + 3][ar0] = pa0.w;
            As[nxt][akc + 0][ar1] = pa1.x; As[nxt][akc + 1][ar1] = pa1.y;
            As[nxt][akc + 2][ar1] = pa1.z; As[nxt][akc + 3][ar1] = pa1.w;
            *(float4*)&Bs[nxt][br0][bbc] = pb0;
            *(float4*)&Bs[nxt][br1][bbc] = pb1;
        }
        __syncthreads();
    }

    float4 bb0 = make_float4(0.f, 0.f, 0.f, 0.f);
    float4 bb1 = make_float4(0.f, 0.f, 0.f, 0.f);
    if (bias) {
        bb0 = *(const float4*)(bias + n0 + tx * 8);
        bb1 = *(const float4*)(bias + n0 + tx * 8 + 4);
    }
#pragma unroll
    for (int i = 0; i < 8; i++) {
        int gr = m0 + ty * 8 + i;
        if (gr < M) {
            float4 r0, r1;
            r0.x = acc[i][0] + bb0.x; r0.y = acc[i][1] + bb0.y;
            r0.z = acc[i][2] + bb0.z; r0.w = acc[i][3] + bb0.w;
            r1.x = acc[i][4] + bb1.x; r1.y = acc[i][5] + bb1.y;
            r1.z = acc[i][6] + bb1.z; r1.w = acc[i][7] + bb1.w;
            if (relu) {
                r0.x = fmaxf(r0.x, 0.f); r0.y = fmaxf(r0.y, 0.f);
                r0.z = fmaxf(r0.z, 0.f); r0.w = fmaxf(r0.w, 0.f);
                r1.x = fmaxf(r1.x, 0.f); r1.y = fmaxf(r1.y, 0.f);
                r1.z = fmaxf(r1.z, 0.f); r1.w = fmaxf(r1.w, 0.f);
            }
            *(float4*)(C + (size_t)gr * N + n0 + tx * 8) = r0;
            *(float4*)(C + (size_t)gr * N + n0 + tx * 8 + 4) = r1;
        }
    }
}

// ---------------- layer-2 aggregation fused with node_logits + edge projections + mean ----------------
__global__ __launch_bounds__(256) void agg2_fused_kernel(
    const float* __restrict__ h2, const float* __restrict__ bias,
    const float* __restrict__ npW, const float* __restrict__ npb,
    const float* __restrict__ epW,
    float* __restrict__ hemb, float* __restrict__ node_logits)
{
    __shared__ float gsum[128];
    const int tid = threadIdx.x;
    if (tid < 128) gsum[tid] = 0.f;
    __syncthreads();

    const int lane = tid & 31;
    int warp = (blockIdx.x * blockDim.x + tid) >> 5;
    const int nw = (gridDim.x * blockDim.x) >> 5;
    const int k = lane * 4;

    float w0[4], w1[4], w2[4];        // node-logit weights (3 cols)
    float es0[4], es1[4], ed0[4], ed1[4];  // edge-proj weights: src rows 0..127, dst rows 128..255
#pragma unroll
    for (int j = 0; j < 4; j++) {
        w0[j] = npW[(k + j) * 3 + 0];
        w1[j] = npW[(k + j) * 3 + 1];
        w2[j] = npW[(k + j) * 3 + 2];
        es0[j] = epW[(k + j) * 2 + 0];
        es1[j] = epW[(k + j) * 2 + 1];
        ed0[j] = epW[(128 + k + j) * 2 + 0];
        ed1[j] = epW[(128 + k + j) * 2 + 1];
    }
    float nb0 = npb[0], nb1 = npb[1], nb2 = npb[2];
    float4 bs = ((const float4*)bias)[lane];
    float gl0 = 0.f, gl1 = 0.f, gl2 = 0.f, gl3 = 0.f;
    const float4* __restrict__ H = (const float4*)h2;

    for (int d = warp; d < NN; d += nw) {
        float dd = g_dinv[d];
        int e0 = g_off[d], e1 = g_off[d + 1];
        float4 acc = make_float4(0.f, 0.f, 0.f, 0.f);
        for (int e = e0; e < e1; e++) {
            int s = g_srcs[e];
            float nm = g_dinv[s] * dd;
            float4 v = H[(size_t)s * 32 + lane];
            acc.x = fmaf(v.x, nm, acc.x); acc.y = fmaf(v.y, nm, acc.y);
            acc.z = fmaf(v.z, nm, acc.z); acc.w = fmaf(v.w, nm, acc.w);
        }
        float sn = dd * dd;
        float4 v = H[(size_t)d * 32 + lane];
        acc.x = fmaf(v.x, sn, acc.x); acc.y = fmaf(v.y, sn, acc.y);
        acc.z = fmaf(v.z, sn, acc.z); acc.w = fmaf(v.w, sn, acc.w);
        acc.x = fmaxf(acc.x + bs.x, 0.f); acc.y = fmaxf(acc.y + bs.y, 0.f);
        acc.z = fmaxf(acc.z + bs.z, 0.f); acc.w = fmaxf(acc.w + bs.w, 0.f);
        ((float4*)hemb)[(size_t)d * 32 + lane] = acc;

        gl0 += acc.x; gl1 += acc.y; gl2 += acc.z; gl3 += acc.w;

        float l0 = acc.x * w0[0] + acc.y * w0[1] + acc.z * w0[2] + acc.w * w0[3];
        float l1 = acc.x * w1[0] + acc.y * w1[1] + acc.z * w1[2] + acc.w * w1[3];
        float l2 = acc.x * w2[0] + acc.y * w2[1] + acc.z * w2[2] + acc.w * w2[3];
        float p0 = acc.x * es0[0] + acc.y * es0[1] + acc.z * es0[2] + acc.w * es0[3];
        float p1 = acc.x * es1[0] + acc.y * es1[1] + acc.z * es1[2] + acc.w * es1[3];
        float q0 = acc.x * ed0[0] + acc.y * ed0[1] + acc.z * ed0[2] + acc.w * ed0[3];
        float q1 = acc.x * ed1[0] + acc.y * ed1[1] + acc.z * ed1[2] + acc.w * ed1[3];
#pragma unroll
        for (int o = 16; o > 0; o >>= 1) {
            l0 += __shfl_down_sync(0xffffffffu, l0, o);
            l1 += __shfl_down_sync(0xffffffffu, l1, o);
            l2 += __shfl_down_sync(0xffffffffu, l2, o);
            p0 += __shfl_down_sync(0xffffffffu, p0, o);
            p1 += __shfl_down_sync(0xffffffffu, p1, o);
            q0 += __shfl_down_sync(0xffffffffu, q0, o);
            q1 += __shfl_down_sync(0xffffffffu, q1, o);
        }
        if (lane == 0) {
            node_logits[(size_t)d * 3 + 0] = l0 + nb0;
            node_logits[(size_t)d * 3 + 1] = l1 + nb1;
            node_logits[(size_t)d * 3 + 2] = l2 + nb2;
            g_proj[d] = make_float4(p0, p1, q0, q1);
        }
    }
    atomicAdd(&gsum[k + 0], gl0);
    atomicAdd(&gsum[k + 1], gl1);
    atomicAdd(&gsum[k + 2], gl2);
    atomicAdd(&gsum[k + 3], gl3);
    __syncthreads();
    if (tid < 128) atomicAdd(&g_gacc[tid], gsum[tid]);
}

// ---------------- edge head via per-node projections: thread per edge ----------------
__global__ __launch_bounds__(256) void edge2_kernel(
    const int* __restrict__ src, const int* __restrict__ dst,
    const float* __restrict__ epb, float* __restrict__ out)
{
    int e = blockIdx.x * blockDim.x + threadIdx.x;
    if (e >= NE) return;
    float4 a = g_proj[src[e]];
    float4 b = g_proj[dst[e]];
    float2 r;
    r.x = a.x + b.z + epb[0];
    r.y = a.y + b.w + epb[1];
    *(float2*)(out + (size_t)e * 2) = r;
}

// ---------------- tiny global heads (value, global_logits) ----------------
__global__ __launch_bounds__(256) void head_kernel(
    const float* __restrict__ fc1W, const float* __restrict__ fc1b,
    const float* __restrict__ fc2W, const float* __restrict__ fc2b,
    const float* __restrict__ gpW, const float* __restrict__ gpb,
    float* __restrict__ out_glob, float* __restrict__ out_value)
{
    __shared__ float g[128];
    __shared__ float vsh[256];
    __shared__ float red[8];
    const int t = threadIdx.x;
    const int lane = t & 31, wid = t >> 5;
    if (t < 128) g[t] = g_gacc[t] * (1.0f / (float)NN);
    __syncthreads();

    float acc = 0.f;
    for (int kk = 0; kk < 128; kk++) acc = fmaf(g[kk], fc1W[kk * 256 + t], acc);
    vsh[t] = fmaxf(acc + fc1b[t], 0.f);
    __syncthreads();

    float p = vsh[t] * fc2W[t];
#pragma unroll
    for (int o = 16; o > 0; o >>= 1) p += __shfl_down_sync(0xffffffffu, p, o);
    if (lane == 0) red[wid] = p;
    __syncthreads();
    if (t == 0) {
        float tot = 0.f;
        for (int i = 0; i < 8; i++) tot += red[i];
        out_value[0] = tot + fc2b[0];
    }
    __syncthreads();

    float q = (t < 128) ? g[t] * gpW[t] : 0.f;
#pragma unroll
    for (int o = 16; o > 0; o >>= 1) q += __shfl_down_sync(0xffffffffu, q, o);
    if (lane == 0) red[wid] = q;
    __syncthreads();
    if (t == 0) {
        float tot = 0.f;
        for (int i = 0; i < 8; i++) tot += red[i];
        out_glob[0] = tot + gpb[0];
    }
}

// ---------------- launch ----------------
extern "C" void kernel_launch(void* const* d_in, const int* in_sizes, int n_in,
                              void* d_out, int out_size)
{
    const float* x    = (const float*)d_in[0];
    const int*   ei   = (const int*)d_in[1];
    const float* W1   = (const float*)d_in[2];
    const float* b1   = (const float*)d_in[3];
    const float* W2   = (const float*)d_in[4];
    const float* b2   = (const float*)d_in[5];
    const float* fc1W = (const float*)d_in[6];
    const float* fc1b = (const float*)d_in[7];
    const float* fc2W = (const float*)d_in[8];
    const float* fc2b = (const float*)d_in[9];
    const float* npW  = (const float*)d_in[10];
    const float* npb  = (const float*)d_in[11];
    const float* epW  = (const float*)d_in[12];
    const float* epb  = (const float*)d_in[13];
    const float* gpW  = (const float*)d_in[14];
    const float* gpb  = (const float*)d_in[15];

    float* out = (float*)d_out;
    float* out_node  = out;
    float* out_edge  = out + (size_t)NN * 3;
    float* out_glob  = out + (size_t)NN * 3 + (size_t)NE * 2;
    float* out_value = out_glob + 1;

    const int* src = ei;
    const int* dst = ei + NE;

    float* buf1; float* buf2;
    void* p;
    cudaGetSymbolAddress(&p, g_buf1); buf1 = (float*)p;
    cudaGetSymbolAddress(&p, g_buf2); buf2 = (float*)p;
    void* pdeg;  cudaGetSymbolAddress(&pdeg, g_deg);
    void* pcur;  cudaGetSymbolAddress(&pcur, g_cur);
    void* pgacc; cudaGetSymbolAddress(&pgacc, g_gacc);

    cudaMemsetAsync(pdeg, 0, NN * sizeof(int));
    cudaMemsetAsync(pcur, 0, NN * sizeof(int));
    cudaMemsetAsync(pgacc, 0, 128 * sizeof(float));

    deg_kernel<<<(NE + 255) / 256, 256>>>(dst);
    scan1_kernel<<<NB, 1024>>>();
    scan2_kernel<<<NB, 1024>>>();
    fill_kernel<<<(NE + 255) / 256, 256>>>(src, dst);

    // zx = A_hat @ x   [N,128]
    aggx_kernel<<<(NN * 32 + 255) / 256, 256>>>(x, buf1);
    // h = relu(zx @ W1 + b1)  [N,256]
    sgemm128_kernel<<<dim3(2, (NN + 127) / 128), 256>>>(buf1, W1, buf2, b1, 1, NN, 256, 128);
    // h2 = h @ W2  [N,128]
    sgemm128_kernel<<<dim3(1, (NN + 127) / 128), 256>>>(buf2, W2, buf1, nullptr, 0, NN, 128, 256);
    // h_emb = relu(agg(h2) + b2); node_logits; edge projections; mean partials
    agg2_fused_kernel<<<1024, 256>>>(buf1, b2, npW, npb, epW, buf2, out_node);
    // edge logits from projections
    edge2_kernel<<<(NE + 255) / 256, 256>>>(src, dst, epb, out_edge);
    // value + global logits
    head_kernel<<<1, 256>>>(fc1W, fc1b, fc2W, fc2b, gpW, gpb, out_glob, out_value);
}